// round 2
// baseline (speedup 1.0000x reference)
#include <cuda_runtime.h>

#define BATCH 16384
#define DIM   2048
#define NEXP  64
#define BM    64
#define BK    32
#define NTHREADS 256
#define XS_STR 66   // even -> 8B-aligned float2 rows; (2k+r)%32 bank spread on stores
#define WS_STR 68   // 68*4 bytes multiple of 16 -> aligned float4 rows
#define LG_STR 68

// Packed dual-fp32 FMA (FFMA2). Only reachable via PTX fma.rn.f32x2.
__device__ __forceinline__ void ffma2(unsigned long long& acc,
                                      unsigned long long a,
                                      unsigned long long w) {
    asm("fma.rn.f32x2 %0, %1, %2, %0;" : "+l"(acc) : "l"(a), "l"(w));
}

union __align__(16) Smem {
    struct {
        float xs[BK][XS_STR];   // x tile, transposed: xs[k][row]
        float ws[BK][WS_STR];   // W tile, transposed: ws[k][expert]
    } g;
    float logits[BM][LG_STR];   // epilogue reuse
};

__global__ __launch_bounds__(NTHREADS)
void topk_gate_kernel(const float* __restrict__ x,
                      const float* __restrict__ W,
                      const float* __restrict__ bias,
                      float* __restrict__ out) {
    __shared__ Smem sm;
    const int tid  = threadIdx.x;
    const int row0 = blockIdx.x * BM;
    const int ty   = tid >> 4;   // 0..15 : row group (4 rows, as 2 row-pairs)
    const int tx   = tid & 15;   // 0..15 : expert group (4 experts)

    // acc[i][j]: row-pair i (rows ty*4+2i, ty*4+2i+1), expert tx*4+j
    unsigned long long acc[2][4];
    #pragma unroll
    for (int i = 0; i < 2; i++)
        #pragma unroll
        for (int j = 0; j < 4; j++) acc[i][j] = 0ull;   // bit pattern of (0.f, 0.f)

    for (int k0 = 0; k0 < DIM; k0 += BK) {
        __syncthreads();   // previous compute must finish before smem overwrite
        // ---- load x tile: 64 rows x 32 k, transpose into xs[k][row] ----
        #pragma unroll
        for (int p = 0; p < 2; p++) {
            int t  = tid + p * NTHREADS;     // 0..511 float4 slots
            int r  = t >> 3;                 // 0..63
            int kk = (t & 7) << 2;           // 0,4,...,28
            float4 v = *(const float4*)(x + (size_t)(row0 + r) * DIM + k0 + kk);
            sm.g.xs[kk + 0][r] = v.x;
            sm.g.xs[kk + 1][r] = v.y;
            sm.g.xs[kk + 2][r] = v.z;
            sm.g.xs[kk + 3][r] = v.w;
        }
        // ---- load W tile: 64 experts x 32 k, transpose into ws[k][e] ----
        #pragma unroll
        for (int p = 0; p < 2; p++) {
            int t  = tid + p * NTHREADS;
            int e  = t >> 3;                 // 0..63
            int kk = (t & 7) << 2;
            float4 v = *(const float4*)(W + (size_t)e * DIM + k0 + kk);
            sm.g.ws[kk + 0][e] = v.x;
            sm.g.ws[kk + 1][e] = v.y;
            sm.g.ws[kk + 2][e] = v.z;
            sm.g.ws[kk + 3][e] = v.w;
        }
        __syncthreads();
        // ---- compute: 32 k-steps, 8 FFMA2 each ----
        #pragma unroll
        for (int k = 0; k < BK; k++) {
            unsigned long long a2[2];
            a2[0] = *(const unsigned long long*)&sm.g.xs[k][ty * 4];
            a2[1] = *(const unsigned long long*)&sm.g.xs[k][ty * 4 + 2];
            float4 w4 = *(const float4*)&sm.g.ws[k][tx * 4];
            float wv[4] = {w4.x, w4.y, w4.z, w4.w};
            #pragma unroll
            for (int j = 0; j < 4; j++) {
                float2 wd = make_float2(wv[j], wv[j]);
                unsigned long long wdl = *(unsigned long long*)&wd;
                ffma2(acc[0][j], a2[0], wdl);
                ffma2(acc[1][j], a2[1], wdl);
            }
        }
    }

    __syncthreads();   // all compute reads done; smem becomes the logits buffer

    // ---- scatter accumulators (+bias) into logits smem ----
    float bv[4];
    #pragma unroll
    for (int j = 0; j < 4; j++) bv[j] = bias[tx * 4 + j];
    #pragma unroll
    for (int i = 0; i < 2; i++) {
        #pragma unroll
        for (int j = 0; j < 4; j++) {
            float2 a = *(float2*)&acc[i][j];
            sm.logits[ty * 4 + 2 * i    ][tx * 4 + j] = a.x + bv[j];
            sm.logits[ty * 4 + 2 * i + 1][tx * 4 + j] = a.y + bv[j];
        }
    }
    __syncthreads();

    // ---- per-row top-2 + softmax (threads 0..63, one row each) ----
    if (tid < BM) {
        const int r = tid;
        float l1 = -1e30f, l2 = -1e30f;
        int   i1 = 0,      i2 = 0;
        #pragma unroll 8
        for (int e = 0; e < NEXP; e++) {
            float v = sm.logits[r][e];
            if (v > l1)      { l2 = l1; i2 = i1; l1 = v; i1 = e; }   // strict > keeps
            else if (v > l2) { l2 = v;  i2 = e; }                    // earliest index on ties
        }
        float e2    = expf(l2 - l1);       // l2 <= l1, safe
        float denom = 1.0f + e2;
        float g1    = 1.0f / denom;
        float g2    = e2 / denom;
        const int gr = row0 + r;
        // layout: gates [BATCH,2] then indices [BATCH,2] (as float)
        out[2 * gr]                 = g1;
        out[2 * gr + 1]             = g2;
        out[2 * BATCH + 2 * gr]     = (float)i1;
        out[2 * BATCH + 2 * gr + 1] = (float)i2;
    }
}

extern "C" void kernel_launch(void* const* d_in, const int* in_sizes, int n_in,
                              void* d_out, int out_size) {
    const float* x = (const float*)d_in[0];
    const float* W = (const float*)d_in[1];
    const float* b = (const float*)d_in[2];
    float* out = (float*)d_out;
    (void)in_sizes; (void)n_in; (void)out_size;
    topk_gate_kernel<<<BATCH / BM, NTHREADS>>>(x, W, b, out);
}

// round 3
// speedup vs baseline: 1.6870x; 1.6870x over previous
#include <cuda_runtime.h>

#define BATCH 16384
#define DIM   2048
#define NEXP  64
#define BM    64
#define BK    32
#define NTHREADS 128
#define NTILES (DIM / BK)      // 64
#define XS_STR 132             // xs2[kf2][4*r2+q], 16B-aligned rows, conflict-free
#define WS_STR 34              // ws[e][k], stride 34 -> conflict-free f2 ld/st
#define LG_STR 68

// Packed dual-fp32 FMA (FFMA2). Only reachable via PTX fma.rn.f32x2.
__device__ __forceinline__ void ffma2(unsigned long long& acc,
                                      unsigned long long a,
                                      unsigned long long w) {
    asm("fma.rn.f32x2 %0, %1, %2, %0;" : "+l"(acc) : "l"(a), "l"(w));
}
__device__ __forceinline__ unsigned long long dup2(float v) {
    float2 d = make_float2(v, v);
    return *(unsigned long long*)&d;
}
__device__ __forceinline__ unsigned long long pack2(float a, float b) {
    float2 d = make_float2(a, b);
    return *(unsigned long long*)&d;
}

union __align__(16) Smem {
    struct {
        float xs[BK / 2][XS_STR];   // interleaved row-pair x tile
        float ws[NEXP][WS_STR];     // W tile, row-major [expert][k]
    } g;
    float logits[BM][LG_STR];       // epilogue reuse
};

__global__ __launch_bounds__(NTHREADS)
void topk_gate_kernel(const float* __restrict__ x,
                      const float* __restrict__ W,
                      const float* __restrict__ bias,
                      float* __restrict__ out) {
    __shared__ Smem sm;
    const int tid  = threadIdx.x;
    const int row0 = blockIdx.x * BM;
    const int ty   = tid >> 4;          // 0..7 : row group (8 rows = 4 pairs)
    const int tx   = tid & 15;          // 0..15: experts {tx,16+tx,32+tx,48+tx}

    // acc[p][j]: rows (ty*8+2p, ty*8+2p+1), expert 16*j+tx
    unsigned long long acc[4][4];
    #pragma unroll
    for (int p = 0; p < 4; p++)
        #pragma unroll
        for (int j = 0; j < 4; j++) acc[p][j] = 0ull;

    // ---- gmem -> register prefetch mappings ----
    const int kf2l = tid & 15;          // f2 slot within tile (k = 2*kf2l, 2*kf2l+1)
    const int r2b  = tid >> 4;          // base row-pair for x loads
    float2 xv[4][2];                    // x[2r][2k..], x[2r+1][2k..] per p
    float2 wv[8];                       // w[e][2k..] per p

    const float* xbase = x + (size_t)row0 * DIM;

#define LOADT(t)                                                              \
    {                                                                         \
        const float* xp = xbase + (t) * BK + 2 * kf2l;                        \
        _Pragma("unroll")                                                     \
        for (int p = 0; p < 4; p++) {                                         \
            int r2 = r2b + 8 * p;                                             \
            xv[p][0] = *(const float2*)(xp + (size_t)(2 * r2) * DIM);         \
            xv[p][1] = *(const float2*)(xp + (size_t)(2 * r2 + 1) * DIM);     \
        }                                                                     \
        const float* wp = W + (t) * BK + 2 * kf2l;                            \
        _Pragma("unroll")                                                     \
        for (int p = 0; p < 8; p++) {                                         \
            int e = r2b + 8 * p;                                              \
            wv[p] = *(const float2*)(wp + (size_t)e * DIM);                   \
        }                                                                     \
    }

    LOADT(0);

    for (int t = 0; t < NTILES; t++) {
        __syncthreads();                 // consumers of previous tile done
        // ---- store prefetched regs into smem ----
        #pragma unroll
        for (int p = 0; p < 4; p++) {
            int r2 = r2b + 8 * p;
            float4 v = make_float4(xv[p][0].x, xv[p][1].x,
                                   xv[p][0].y, xv[p][1].y);
            *(float4*)&sm.g.xs[kf2l][4 * r2] = v;     // conflict-free STS.128
        }
        #pragma unroll
        for (int p = 0; p < 8; p++) {
            int e = r2b + 8 * p;
            *(float2*)&sm.g.ws[e][2 * kf2l] = wv[p];  // conflict-free STS.64
        }
        __syncthreads();

        if (t + 1 < NTILES) LOADT(t + 1);  // LDGs fly during compute

        // ---- compute: 16 double-k steps ----
        #pragma unroll
        for (int kf2 = 0; kf2 < BK / 2; kf2++) {
            float4 a[4];
            #pragma unroll
            for (int p = 0; p < 4; p++)
                a[p] = *(const float4*)&sm.g.xs[kf2][(ty * 4 + p) * 4];  // broadcast
            float2 w2[4];
            #pragma unroll
            for (int j = 0; j < 4; j++)
                w2[j] = *(const float2*)&sm.g.ws[16 * j + tx][2 * kf2];
            #pragma unroll
            for (int j = 0; j < 4; j++) {
                unsigned long long w0 = dup2(w2[j].x);   // ALU-pipe dup
                unsigned long long w1 = dup2(w2[j].y);
                #pragma unroll
                for (int p = 0; p < 4; p++) {
                    ffma2(acc[p][j], pack2(a[p].x, a[p].y), w0);  // zero-cost packs
                    ffma2(acc[p][j], pack2(a[p].z, a[p].w), w1);
                }
            }
        }
    }

    __syncthreads();   // smem becomes logits buffer

    // ---- scatter accumulators (+bias) ----
    #pragma unroll
    for (int j = 0; j < 4; j++) {
        int e = 16 * j + tx;
        float bv = bias[e];
        #pragma unroll
        for (int p = 0; p < 4; p++) {
            float2 a = *(float2*)&acc[p][j];
            sm.logits[ty * 8 + 2 * p    ][e] = a.x + bv;
            sm.logits[ty * 8 + 2 * p + 1][e] = a.y + bv;
        }
    }
    __syncthreads();

    // ---- per-row top-2 + softmax (threads 0..63) ----
    if (tid < BM) {
        const int r = tid;
        float l1 = -1e30f, l2 = -1e30f;
        int   i1 = 0,      i2 = 0;
        #pragma unroll 8
        for (int e = 0; e < NEXP; e++) {
            float v = sm.logits[r][e];
            if (v > l1)      { l2 = l1; i2 = i1; l1 = v; i1 = e; }
            else if (v > l2) { l2 = v;  i2 = e; }
        }
        float e2    = expf(l2 - l1);
        float denom = 1.0f + e2;
        float g1    = 1.0f / denom;
        float g2    = e2 / denom;
        const int gr = row0 + r;
        out[2 * gr]                 = g1;
        out[2 * gr + 1]             = g2;
        out[2 * BATCH + 2 * gr]     = (float)i1;
        out[2 * BATCH + 2 * gr + 1] = (float)i2;
    }
}

extern "C" void kernel_launch(void* const* d_in, const int* in_sizes, int n_in,
                              void* d_out, int out_size) {
    const float* x = (const float*)d_in[0];
    const float* W = (const float*)d_in[1];
    const float* b = (const float*)d_in[2];
    float* out = (float*)d_out;
    (void)in_sizes; (void)n_in; (void)out_size;
    topk_gate_kernel<<<BATCH / BM, NTHREADS>>>(x, W, b, out);
}

// round 5
// speedup vs baseline: 1.7320x; 1.0267x over previous
#include <cuda_runtime.h>

#define BATCH 16384
#define DIM   2048
#define NEXP  64
#define BM    64
#define BK    32
#define KSPLIT 4
#define KPER  (DIM / KSPLIT)     // 512
#define NTILES (KPER / BK)       // 16
#define NTHREADS 128
#define XS_STR 132
#define WS_STR 34
#define LG_STR 68

// 16MB scratch for split-K partial logits: [split][row][expert]
__device__ float g_part[KSPLIT][BATCH][NEXP];

// Packed dual-fp32 FMA (FFMA2). Only reachable via PTX fma.rn.f32x2.
__device__ __forceinline__ void ffma2(unsigned long long& acc,
                                      unsigned long long a,
                                      unsigned long long w) {
    asm("fma.rn.f32x2 %0, %1, %2, %0;" : "+l"(acc) : "l"(a), "l"(w));
}
__device__ __forceinline__ unsigned long long dup2(float v) {
    float2 d = make_float2(v, v);
    return *(unsigned long long*)&d;
}
__device__ __forceinline__ unsigned long long pack2(float a, float b) {
    float2 d = make_float2(a, b);
    return *(unsigned long long*)&d;
}

union __align__(16) Smem {
    struct {
        float xs[BK / 2][XS_STR];   // interleaved row-pair x tile
        float ws[NEXP][WS_STR];     // W tile, row-major [expert][k]
    } g;
    float logits[BM][LG_STR];       // epilogue staging
};

__global__ __launch_bounds__(NTHREADS)
void gemm_partial_kernel(const float* __restrict__ x,
                         const float* __restrict__ W) {
    __shared__ Smem sm;
    const int tid  = threadIdx.x;
    const int row0 = blockIdx.x * BM;
    const int ks   = blockIdx.y;          // k-split id
    const int kbase = ks * KPER;
    const int ty   = tid >> 4;            // 0..7 : 8 rows (4 pairs)
    const int tx   = tid & 15;            // 0..15: experts {tx,16+tx,32+tx,48+tx}

    unsigned long long acc[4][4];
    #pragma unroll
    for (int p = 0; p < 4; p++)
        #pragma unroll
        for (int j = 0; j < 4; j++) acc[p][j] = 0ull;

    const int kf2l = tid & 15;
    const int r2b  = tid >> 4;
    float2 xv[4][2];
    float2 wv[8];
    const float* xbase = x + (size_t)row0 * DIM + kbase;
    const float* wbase = W + kbase;

#define LOADT(t)                                                              \
    {                                                                         \
        const float* xp = xbase + (t) * BK + 2 * kf2l;                        \
        _Pragma("unroll")                                                     \
        for (int p = 0; p < 4; p++) {                                         \
            int r2 = r2b + 8 * p;                                             \
            xv[p][0] = *(const float2*)(xp + (size_t)(2 * r2) * DIM);         \
            xv[p][1] = *(const float2*)(xp + (size_t)(2 * r2 + 1) * DIM);     \
        }                                                                     \
        const float* wp = wbase + (t) * BK + 2 * kf2l;                        \
        _Pragma("unroll")                                                     \
        for (int p = 0; p < 8; p++) {                                         \
            int e = r2b + 8 * p;                                              \
            wv[p] = *(const float2*)(wp + (size_t)e * DIM);                   \
        }                                                                     \
    }

    LOADT(0);

    for (int t = 0; t < NTILES; t++) {
        __syncthreads();
        #pragma unroll
        for (int p = 0; p < 4; p++) {
            int r2 = r2b + 8 * p;
            float4 v = make_float4(xv[p][0].x, xv[p][1].x,
                                   xv[p][0].y, xv[p][1].y);
            *(float4*)&sm.g.xs[kf2l][4 * r2] = v;
        }
        #pragma unroll
        for (int p = 0; p < 8; p++) {
            int e = r2b + 8 * p;
            *(float2*)&sm.g.ws[e][2 * kf2l] = wv[p];
        }
        __syncthreads();

        if (t + 1 < NTILES) LOADT(t + 1);

        #pragma unroll
        for (int kf2 = 0; kf2 < BK / 2; kf2++) {
            float4 a[4];
            #pragma unroll
            for (int p = 0; p < 4; p++)
                a[p] = *(const float4*)&sm.g.xs[kf2][(ty * 4 + p) * 4];
            float2 w2[4];
            #pragma unroll
            for (int j = 0; j < 4; j++)
                w2[j] = *(const float2*)&sm.g.ws[16 * j + tx][2 * kf2];
            #pragma unroll
            for (int j = 0; j < 4; j++) {
                unsigned long long w0 = dup2(w2[j].x);
                unsigned long long w1 = dup2(w2[j].y);
                #pragma unroll
                for (int p = 0; p < 4; p++) {
                    ffma2(acc[p][j], pack2(a[p].x, a[p].y), w0);
                    ffma2(acc[p][j], pack2(a[p].z, a[p].w), w1);
                }
            }
        }
    }

    __syncthreads();   // smem becomes staging buffer

    // stage partial logits in smem for coalesced global writes
    #pragma unroll
    for (int j = 0; j < 4; j++) {
        int e = 16 * j + tx;
        #pragma unroll
        for (int p = 0; p < 4; p++) {
            float2 a = *(float2*)&acc[p][j];
            sm.logits[ty * 8 + 2 * p    ][e] = a.x;
            sm.logits[ty * 8 + 2 * p + 1][e] = a.y;
        }
    }
    __syncthreads();

    // coalesced store: thread t writes 8 float4 (row = t>>1, half = t&1)
    {
        const int r = tid >> 1;
        const int h = tid & 1;
        float* dst = &g_part[ks][row0 + r][h * 32];
        #pragma unroll
        for (int i = 0; i < 8; i++) {
            float4 v = *(const float4*)&sm.logits[r][h * 32 + 4 * i];
            *(float4*)(dst + 4 * i) = v;
        }
    }
}

__global__ __launch_bounds__(128)
void reduce_topk_kernel(const float* __restrict__ bias,
                        float* __restrict__ out) {
    const int row = blockIdx.x * 128 + threadIdx.x;
    float l1 = -1e30f, l2 = -1e30f;
    int   i1 = 0,      i2 = 0;
    #pragma unroll
    for (int e4 = 0; e4 < NEXP / 4; e4++) {
        float4 s = *(const float4*)&g_part[0][row][4 * e4];
        #pragma unroll
        for (int ks = 1; ks < KSPLIT; ks++) {
            float4 p = *(const float4*)&g_part[ks][row][4 * e4];
            s.x += p.x; s.y += p.y; s.z += p.z; s.w += p.w;
        }
        float4 bv = *(const float4*)&bias[4 * e4];
        float v[4] = {s.x + bv.x, s.y + bv.y, s.z + bv.z, s.w + bv.w};
        #pragma unroll
        for (int c = 0; c < 4; c++) {
            int e = 4 * e4 + c;
            if (v[c] > l1)      { l2 = l1; i2 = i1; l1 = v[c]; i1 = e; }
            else if (v[c] > l2) { l2 = v[c]; i2 = e; }
        }
    }
    float e2    = expf(l2 - l1);
    float denom = 1.0f + e2;
    out[2 * row]                 = 1.0f / denom;
    out[2 * row + 1]             = e2 / denom;
    out[2 * BATCH + 2 * row]     = (float)i1;
    out[2 * BATCH + 2 * row + 1] = (float)i2;
}

extern "C" void kernel_launch(void* const* d_in, const int* in_sizes, int n_in,
                              void* d_out, int out_size) {
    const float* x = (const float*)d_in[0];
    const float* W = (const float*)d_in[1];
    const float* b = (const float*)d_in[2];
    float* out = (float*)d_out;
    (void)in_sizes; (void)n_in; (void)out_size;
    gemm_partial_kernel<<<dim3(BATCH / BM, KSPLIT), NTHREADS>>>(x, W);
    reduce_topk_kernel<<<BATCH / 128, 128>>>(b, out);
}